// round 9
// baseline (speedup 1.0000x reference)
#include <cuda_runtime.h>
#include <cuda_fp16.h>

// DiffeomorphicTransform: scaling-and-squaring, 7 steps.
// R7: back to 1 voxel/thread (R5 shape, occupancy-bound insight) +
//     neighbor-pair fp16 records: rec[v] = (f(v), f(v+1)) in 16B, so each
//     (z,y) corner-row needs ONE LDG.128 instead of two 8B gathers (8 -> 4).

#define DD 128
#define HH 160
#define WW 128
#define NVOX (DD * HH * WW)          // 2,621,440
#define NELEM (3 * NVOX)

// Ping-pong scratch (no cudaMalloc allowed).
__device__ float g_fA[NELEM];        // planar fp32 carry
__device__ float g_fB[NELEM];
__device__ uint4 g_hA[NVOX];         // pair records: (fx0,fy0)(fz0,fx1)(fy1,fz1)(pad)
__device__ uint4 g_hB[NVOX];

__device__ __forceinline__ unsigned int h2u(float a, float b) {
    __half2 h = __floats2half2_rn(a, b);
    return *reinterpret_cast<unsigned int*>(&h);
}

__device__ __forceinline__ uint4 pack_rec(float ax, float ay, float az,
                                          float bx, float by, float bz) {
    uint4 r;
    r.x = h2u(ax, ay);
    r.y = h2u(az, bx);
    r.z = h2u(by, bz);
    r.w = 0u;
    return r;
}

// x-lerp of the record's two voxels: a + wx*(b-a), per component, in fp32.
__device__ __forceinline__ float3 lerp_pair(uint4 rec, float wx) {
    __half2 h0 = *reinterpret_cast<__half2*>(&rec.x);
    __half2 h1 = *reinterpret_cast<__half2*>(&rec.y);
    __half2 h2 = *reinterpret_cast<__half2*>(&rec.z);
    float2 f0 = __half22float2(h0);   // ax, ay
    float2 f1 = __half22float2(h1);   // az, bx
    float2 f2 = __half22float2(h2);   // by, bz
    return make_float3(fmaf(wx, f1.y - f0.x, f0.x),
                       fmaf(wx, f2.x - f0.y, f0.y),
                       fmaf(wx, f2.y - f1.x, f1.x));
}

// planar velocity -> planar fp32 (scaled 1/128) + pair records (runs once)
__global__ void __launch_bounds__(256) convert_kernel(
    const float* __restrict__ vel, float* __restrict__ out, uint4* __restrict__ outh)
{
    int v = blockIdx.x * blockDim.x + threadIdx.x;
    if (v >= NVOX) return;
    const float s = 1.0f / 128.0f;
    const float fx = vel[v] * s;
    const float fy = vel[NVOX + v] * s;
    const float fz = vel[2 * NVOX + v] * s;
    out[v]            = fx;
    out[NVOX + v]     = fy;
    out[2 * NVOX + v] = fz;

    const int x = v & (WW - 1);
    float nx = fx, ny = fy, nz = fz;
    if (x < WW - 1) {              // neighbor is in-bounds; else wx==0 path (value unused)
        nx = vel[v + 1] * s;
        ny = vel[NVOX + v + 1] * s;
        nz = vel[2 * NVOX + v + 1] * s;
    }
    outh[v] = pack_rec(fx, fy, fz, nx, ny, nz);
}

template <bool LAST>
__global__ void __launch_bounds__(256) step_kernel(
    const float* __restrict__ fin,     // planar fp32 carry
    const uint4* __restrict__ hin,     // pair records (gather source)
    const float* __restrict__ rfp,
    float* __restrict__ fout,          // planar fp32 (dst buffer or d_out)
    uint4* __restrict__ houth)         // pair records out (unused on last)
{
    // Grid is exact: gridDim.x*256 == NVOX, all threads live (needed for shfl).
    const int v = blockIdx.x * blockDim.x + threadIdx.x;

    const float rf = __ldg(rfp);
    const float sx = rf * 0.5f * (float)(WW - 1);
    const float sy = rf * 0.5f * (float)(HH - 1);
    const float sz = rf * 0.5f * (float)(DD - 1);

    // voxel coords (W=128 power of two)
    const int x = v & (WW - 1);
    const int rest = v >> 7;
    const int y = rest % HH;
    const int z = rest / HH;

    const float fx = fin[v];
    const float fy = fin[NVOX + v];
    const float fz = fin[2 * NVOX + v];

    float ix = fmaf(fx, sx, (float)x);
    float iy = fmaf(fy, sy, (float)y);
    float iz = fmaf(fz, sz, (float)z);
    ix = fminf(fmaxf(ix, 0.0f), (float)(WW - 1));
    iy = fminf(fmaxf(iy, 0.0f), (float)(HH - 1));
    iz = fminf(fmaxf(iz, 0.0f), (float)(DD - 1));

    const float x0f = floorf(ix), y0f = floorf(iy), z0f = floorf(iz);
    const float wx = ix - x0f, wy = iy - y0f, wz = iz - z0f;
    const int x0 = (int)x0f, y0 = (int)y0f, z0 = (int)z0f;
    const int y1 = min(y0 + 1, HH - 1);
    const int z1 = min(z0 + 1, DD - 1);
    // NOTE: no x1 — the pair record supplies (x0, x0+1); when x0==W-1, wx==0
    // so the (possibly row-crossing) second lane has zero weight and is finite.

    const int b00 = (z0 * HH + y0) * WW + x0;
    const int b01 = (z0 * HH + y1) * WW + x0;
    const int b10 = (z1 * HH + y0) * WW + x0;
    const int b11 = (z1 * HH + y1) * WW + x0;

    const float3 m00 = lerp_pair(__ldg(&hin[b00]), wx);
    const float3 m01 = lerp_pair(__ldg(&hin[b01]), wx);
    const float3 m10 = lerp_pair(__ldg(&hin[b10]), wx);
    const float3 m11 = lerp_pair(__ldg(&hin[b11]), wx);

    const float owy = 1.0f - wy, owz = 1.0f - wz;
    const float w00 = owz * owy, w01 = owz * wy, w10 = wz * owy, w11 = wz * wy;

    float rx = fx, ry = fy, rz = fz;
    rx = fmaf(w00, m00.x, rx); ry = fmaf(w00, m00.y, ry); rz = fmaf(w00, m00.z, rz);
    rx = fmaf(w01, m01.x, rx); ry = fmaf(w01, m01.y, ry); rz = fmaf(w01, m01.z, rz);
    rx = fmaf(w10, m10.x, rx); ry = fmaf(w10, m10.y, ry); rz = fmaf(w10, m10.z, rz);
    rx = fmaf(w11, m11.x, rx); ry = fmaf(w11, m11.y, ry); rz = fmaf(w11, m11.z, rz);

    fout[v]            = rx;
    fout[NVOX + v]     = ry;
    fout[2 * NVOX + v] = rz;

    if (!LAST) {
        // Build pair record: need f(v+1) of THIS step's output.
        // Intra-warp: shfl_down. Lane 31: warps whose lane31 x==127 need no
        // neighbor (wx==0 case); others take next warp's lane0 via smem.
        __shared__ float3 s_lane0[8];
        const int wid  = threadIdx.x >> 5;
        const int lane = threadIdx.x & 31;
        if (lane == 0) s_lane0[wid] = make_float3(rx, ry, rz);
        __syncthreads();

        float nx = __shfl_down_sync(0xFFFFFFFFu, rx, 1);
        float ny = __shfl_down_sync(0xFFFFFFFFu, ry, 1);
        float nz = __shfl_down_sync(0xFFFFFFFFu, rz, 1);
        if (lane == 31) {
            if ((wid & 3) != 3) {          // lane31 x != 127 -> real neighbor
                float3 t = s_lane0[wid + 1];
                nx = t.x; ny = t.y; nz = t.z;
            } else {                       // x == 127: value never weighted
                nx = rx; ny = ry; nz = rz;
            }
        }
        houth[v] = pack_rec(rx, ry, rz, nx, ny, nz);
    }
}

extern "C" void kernel_launch(void* const* d_in, const int* in_sizes, int n_in,
                              void* d_out, int out_size) {
    (void)in_sizes; (void)n_in; (void)out_size;
    const float* velocity = (const float*)d_in[0];
    const float* rf       = (const float*)d_in[2];
    float* out            = (float*)d_out;

    float *fA, *fB;
    uint4 *hA, *hB;
    cudaGetSymbolAddress((void**)&fA, g_fA);
    cudaGetSymbolAddress((void**)&fB, g_fB);
    cudaGetSymbolAddress((void**)&hA, g_hA);
    cudaGetSymbolAddress((void**)&hB, g_hB);

    const int T = 256;
    const int G = NVOX / T;   // exact: 10240

    convert_kernel<<<G, T>>>(velocity, fA, hA);

    float* src = fA;  uint4* hsrc = hA;
    float* dst = fB;  uint4* hdst = hB;
    for (int it = 0; it < 6; it++) {
        step_kernel<false><<<G, T>>>(src, hsrc, rf, dst, hdst);
        float* t1 = src; src = dst; dst = t1;
        uint4* t2 = hsrc; hsrc = hdst; hdst = t2;
    }
    step_kernel<true><<<G, T>>>(src, hsrc, rf, out, nullptr);
}

// round 13
// speedup vs baseline: 1.1977x; 1.1977x over previous
#include <cuda_runtime.h>
#include <cuda_fp16.h>

// DiffeomorphicTransform: scaling-and-squaring, 7 steps.
// R8: R5 step shape (best so far: 1 vox/thread, planar fp32 carry, 8B fp16
//     mirror gathers) +
//   - convert pass writes ONLY the mirror (first step reads velocity directly
//     with the 1/128 scale fused)  -> saves ~10us
//   - __ldcs/__stcs on the planar fp32 streams (evict-first) to keep the fp16
//     mirrors resident in L2 for the scattered gathers.

#define DD 128
#define HH 160
#define WW 128
#define NVOX (DD * HH * WW)          // 2,621,440
#define NELEM (3 * NVOX)

// Ping-pong scratch (no cudaMalloc allowed).
__device__ float g_fA[NELEM];        // planar fp32 carry
__device__ float g_fB[NELEM];
__device__ uint2 g_hA[NVOX];         // fp16 mirror: half2(x,y), half2(z,0)
__device__ uint2 g_hB[NVOX];

__device__ __forceinline__ uint2 pack_h(float x, float y, float z) {
    __half2 xy = __floats2half2_rn(x, y);
    __half2 z0 = __floats2half2_rn(z, 0.0f);
    uint2 r;
    r.x = *reinterpret_cast<unsigned int*>(&xy);
    r.y = *reinterpret_cast<unsigned int*>(&z0);
    return r;
}

__device__ __forceinline__ float3 unpack_h(uint2 raw) {
    __half2 xy = *reinterpret_cast<__half2*>(&raw.x);
    __half2 z0 = *reinterpret_cast<__half2*>(&raw.y);
    float2 fxy = __half22float2(xy);
    return make_float3(fxy.x, fxy.y, __low2float(z0));
}

// velocity -> fp16 mirror of flow0 = vel/128 (mirror only; no fp32 write)
__global__ void __launch_bounds__(256) convert_kernel(
    const float* __restrict__ vel, uint2* __restrict__ outh)
{
    int v = blockIdx.x * blockDim.x + threadIdx.x;
    if (v >= NVOX) return;
    const float s = 1.0f / 128.0f;
    outh[v] = pack_h(vel[v] * s, vel[NVOX + v] * s, vel[2 * NVOX + v] * s);
}

template <bool FIRST, bool LAST>
__global__ void __launch_bounds__(256) step_kernel(
    const float* __restrict__ fin,     // planar fp32 carry (velocity if FIRST)
    const uint2* __restrict__ hin,     // fp16 mirror (gather source)
    const float* __restrict__ rfp,
    float* __restrict__ fout,          // planar fp32 (dst buffer or d_out)
    uint2* __restrict__ houth)         // fp16 mirror out (unused on last)
{
    const int v = blockIdx.x * blockDim.x + threadIdx.x;
    if (v >= NVOX) return;

    const float rf = __ldg(rfp);
    const float sx = rf * 0.5f * (float)(WW - 1);
    const float sy = rf * 0.5f * (float)(HH - 1);
    const float sz = rf * 0.5f * (float)(DD - 1);

    // voxel coords (W=128 power of two)
    const int x = v & (WW - 1);
    const int rest = v >> 7;
    const int y = rest % HH;
    const int z = rest / HH;

    // self flow: streaming loads (evict-first) — keep L2 for the mirrors.
    float fx = __ldcs(&fin[v]);
    float fy = __ldcs(&fin[NVOX + v]);
    float fz = __ldcs(&fin[2 * NVOX + v]);
    if (FIRST) {
        const float s = 1.0f / 128.0f;
        fx *= s; fy *= s; fz *= s;
    }

    float ix = fmaf(fx, sx, (float)x);
    float iy = fmaf(fy, sy, (float)y);
    float iz = fmaf(fz, sz, (float)z);
    ix = fminf(fmaxf(ix, 0.0f), (float)(WW - 1));
    iy = fminf(fmaxf(iy, 0.0f), (float)(HH - 1));
    iz = fminf(fmaxf(iz, 0.0f), (float)(DD - 1));

    const float x0f = floorf(ix), y0f = floorf(iy), z0f = floorf(iz);
    const float wx = ix - x0f, wy = iy - y0f, wz = iz - z0f;
    const int x0 = (int)x0f, y0 = (int)y0f, z0 = (int)z0f;
    const int x1 = min(x0 + 1, WW - 1);
    const int y1 = min(y0 + 1, HH - 1);
    const int z1 = min(z0 + 1, DD - 1);

    const int b00 = (z0 * HH + y0) * WW;
    const int b01 = (z0 * HH + y1) * WW;
    const int b10 = (z1 * HH + y0) * WW;
    const int b11 = (z1 * HH + y1) * WW;

    const float3 c000 = unpack_h(__ldg(&hin[b00 + x0]));
    const float3 c001 = unpack_h(__ldg(&hin[b00 + x1]));
    const float3 c010 = unpack_h(__ldg(&hin[b01 + x0]));
    const float3 c011 = unpack_h(__ldg(&hin[b01 + x1]));
    const float3 c100 = unpack_h(__ldg(&hin[b10 + x0]));
    const float3 c101 = unpack_h(__ldg(&hin[b10 + x1]));
    const float3 c110 = unpack_h(__ldg(&hin[b11 + x0]));
    const float3 c111 = unpack_h(__ldg(&hin[b11 + x1]));

    const float owx = 1.0f - wx, owy = 1.0f - wy, owz = 1.0f - wz;
    const float w00 = owz * owy, w01 = owz * wy, w10 = wz * owy, w11 = wz * wy;
    const float w000 = w00 * owx, w001 = w00 * wx;
    const float w010 = w01 * owx, w011 = w01 * wx;
    const float w100 = w10 * owx, w101 = w10 * wx;
    const float w110 = w11 * owx, w111 = w11 * wx;

    float rx = fx, ry = fy, rz = fz;
    rx = fmaf(w000, c000.x, rx); ry = fmaf(w000, c000.y, ry); rz = fmaf(w000, c000.z, rz);
    rx = fmaf(w001, c001.x, rx); ry = fmaf(w001, c001.y, ry); rz = fmaf(w001, c001.z, rz);
    rx = fmaf(w010, c010.x, rx); ry = fmaf(w010, c010.y, ry); rz = fmaf(w010, c010.z, rz);
    rx = fmaf(w011, c011.x, rx); ry = fmaf(w011, c011.y, ry); rz = fmaf(w011, c011.z, rz);
    rx = fmaf(w100, c100.x, rx); ry = fmaf(w100, c100.y, ry); rz = fmaf(w100, c100.z, rz);
    rx = fmaf(w101, c101.x, rx); ry = fmaf(w101, c101.y, ry); rz = fmaf(w101, c101.z, rz);
    rx = fmaf(w110, c110.x, rx); ry = fmaf(w110, c110.y, ry); rz = fmaf(w110, c110.z, rz);
    rx = fmaf(w111, c111.x, rx); ry = fmaf(w111, c111.y, ry); rz = fmaf(w111, c111.z, rz);

    if (LAST) {
        fout[v]            = rx;
        fout[NVOX + v]     = ry;
        fout[2 * NVOX + v] = rz;
    } else {
        __stcs(&fout[v],            rx);
        __stcs(&fout[NVOX + v],     ry);
        __stcs(&fout[2 * NVOX + v], rz);
        houth[v] = pack_h(rx, ry, rz);   // mirror: keep cached (hot data)
    }
}

extern "C" void kernel_launch(void* const* d_in, const int* in_sizes, int n_in,
                              void* d_out, int out_size) {
    (void)in_sizes; (void)n_in; (void)out_size;
    const float* velocity = (const float*)d_in[0];
    const float* rf       = (const float*)d_in[2];
    float* out            = (float*)d_out;

    float *fA, *fB;
    uint2 *hA, *hB;
    cudaGetSymbolAddress((void**)&fA, g_fA);
    cudaGetSymbolAddress((void**)&fB, g_fB);
    cudaGetSymbolAddress((void**)&hA, g_hA);
    cudaGetSymbolAddress((void**)&hB, g_hB);

    const int T = 256;
    const int G = NVOX / T;   // exact: 10240

    // mirror of flow0 only (first step reads velocity directly)
    convert_kernel<<<G, T>>>(velocity, hA);

    // step 1: fin = velocity (scaled in-kernel), mirror = hA, out -> fA/hB
    step_kernel<true, false><<<G, T>>>(velocity, hA, rf, fA, hB);

    // steps 2..6
    float* src = fA;  uint2* hsrc = hB;
    float* dst = fB;  uint2* hdst = hA;
    for (int it = 0; it < 5; it++) {
        step_kernel<false, false><<<G, T>>>(src, hsrc, rf, dst, hdst);
        float* t1 = src; src = dst; dst = t1;
        uint2* t2 = hsrc; hsrc = hdst; hdst = t2;
    }
    // step 7 -> d_out
    step_kernel<false, true><<<G, T>>>(src, hsrc, rf, out, nullptr);
}